// round 12
// baseline (speedup 1.0000x reference)
#include <cuda_runtime.h>
#include <cstdint>

// out = y * (mean(x,-1) + mean(y,-1)),  [64, 36, 4096] fp32, rows = 2304.
//
// R11 = resubmission of R10 (infra failure, no measurement). R5 best-known
// structure (persistent 3 CTAs/SM, double-buffered 1D bulk-TMA loads of x,y
// into SMEM, y held in registers) with ONE change vs R5: output stores are
// st.global.wt (write-through). Store-policy sweep is monotonic -- the less
// the 37.7 MB/replay write stream occupies L2, the better the warm time
// (cs 14.4 < normal 18.9 < evict_last 21.2) -- because out-lines displace
// the 75 MB input set whose L2 residency sets the warm equilibrium. wt is
// the furthest point on that axis.

constexpr int L_LEN     = 4096;
constexpr int NTHREADS  = 256;
constexpr int ITERS     = L_LEN / (NTHREADS * 4);   // 4 float4 per thread
constexpr int ROW_BYTES = L_LEN * 4;                // 16 KB
constexpr int STAGE_FLOATS = 2 * L_LEN;             // [x 4096][y 4096], 32 KB
constexpr int DYN_SMEM  = 2 * STAGE_FLOATS * 4;     // two stages, 64 KB

__device__ __forceinline__ uint32_t smem_u32(const void* p) {
    return (uint32_t)__cvta_generic_to_shared(p);
}

__device__ __forceinline__ void mbar_init(uint32_t mbar, uint32_t count) {
    asm volatile("mbarrier.init.shared.b64 [%0], %1;" :: "r"(mbar), "r"(count) : "memory");
}

__device__ __forceinline__ void mbar_expect_tx(uint32_t mbar, uint32_t bytes) {
    asm volatile("mbarrier.arrive.expect_tx.shared.b64 _, [%0], %1;"
                 :: "r"(mbar), "r"(bytes) : "memory");
}

__device__ __forceinline__ void bulk_ld(uint32_t dst_smem, const void* src, uint32_t bytes,
                                        uint32_t mbar) {
    asm volatile(
        "cp.async.bulk.shared::cluster.global.mbarrier::complete_tx::bytes "
        "[%0], [%1], %2, [%3];"
        :: "r"(dst_smem), "l"(src), "r"(bytes), "r"(mbar) : "memory");
}

__device__ __forceinline__ void stg_wt_f4(float4* p, float4 v) {
    asm volatile("st.global.wt.v4.f32 [%0], {%1,%2,%3,%4};"
                 :: "l"(p), "f"(v.x), "f"(v.y), "f"(v.z), "f"(v.w)
                 : "memory");
}

__device__ __forceinline__ void mbar_wait(uint32_t mbar, uint32_t parity) {
    uint32_t done;
    asm volatile(
        "{\n\t"
        ".reg .pred p;\n\t"
        "mbarrier.try_wait.parity.acquire.cta.shared::cta.b64 p, [%1], %2;\n\t"
        "selp.b32 %0, 1, 0, p;\n\t"
        "}"
        : "=r"(done) : "r"(mbar), "r"(parity) : "memory");
    if (!done) {
        asm volatile(
            "{\n\t"
            ".reg .pred P1;\n\t"
            "WAIT_LOOP_%=:\n\t"
            "mbarrier.try_wait.parity.acquire.cta.shared::cta.b64 P1, [%0], %1, 0x989680;\n\t"
            "@P1 bra.uni WAIT_DONE_%=;\n\t"
            "bra.uni WAIT_LOOP_%=;\n\t"
            "WAIT_DONE_%=:\n\t"
            "}"
            :: "r"(mbar), "r"(parity) : "memory");
    }
}

__global__ __launch_bounds__(NTHREADS)
void spo2_wt_kernel(const float* __restrict__ x,
                    const float* __restrict__ y,
                    float* __restrict__ out,
                    int nrows)
{
    extern __shared__ float sbuf[];   // stage s at sbuf + s*STAGE_FLOATS
    __shared__ alignas(8) unsigned long long mbar_storage[2];
    __shared__ float warpsum[NTHREADS / 32];

    const int tid = threadIdx.x;
    const uint32_t mb[2] = { smem_u32(&mbar_storage[0]), smem_u32(&mbar_storage[1]) };

    if (tid == 0) {
        mbar_init(mb[0], 1);
        mbar_init(mb[1], 1);
    }
    __syncthreads();

    const int stride = gridDim.x;
    const int row0 = blockIdx.x;

    // Prologue: row0 into stage 0.
    if (tid == 0 && row0 < nrows) {
        const size_t base = (size_t)row0 * L_LEN;
        mbar_expect_tx(mb[0], 2 * ROW_BYTES);
        bulk_ld(smem_u32(sbuf),         x + base, ROW_BYTES, mb[0]);
        bulk_ld(smem_u32(sbuf + L_LEN), y + base, ROW_BYTES, mb[0]);
    }

    int phase0 = 0, phase1 = 0;
    int k = 0;
    for (int row = row0; row < nrows; row += stride, k++) {
        const int s = k & 1;

        // Issue TMA for the NEXT row into the other stage before waiting.
        const int nrow = row + stride;
        if (tid == 0 && nrow < nrows) {
            const int ns = 1 - s;
            const size_t nbase = (size_t)nrow * L_LEN;
            float* nstage = sbuf + ns * STAGE_FLOATS;
            mbar_expect_tx(mb[ns], 2 * ROW_BYTES);
            bulk_ld(smem_u32(nstage),         x + nbase, ROW_BYTES, mb[ns]);
            bulk_ld(smem_u32(nstage + L_LEN), y + nbase, ROW_BYTES, mb[ns]);
        }

        if (s == 0) { mbar_wait(mb[0], phase0); phase0 ^= 1; }
        else        { mbar_wait(mb[1], phase1); phase1 ^= 1; }

        const float4* sx4 = reinterpret_cast<const float4*>(sbuf + s * STAGE_FLOATS);
        const float4* sy4 = reinterpret_cast<const float4*>(sbuf + s * STAGE_FLOATS + L_LEN);

        float4 yv[ITERS];
        float t = 0.0f;
#pragma unroll
        for (int i = 0; i < ITERS; i++) {
            const int idx = i * NTHREADS + tid;
            float4 a = sx4[idx];
            yv[i] = sy4[idx];
            t += (a.x + a.y) + (a.z + a.w);
            t += (yv[i].x + yv[i].y) + (yv[i].z + yv[i].w);
        }

        // Block reduction -> sc = (sum_x + sum_y)/L
#pragma unroll
        for (int o = 16; o > 0; o >>= 1)
            t += __shfl_xor_sync(0xffffffffu, t, o);
        if ((tid & 31) == 0)
            warpsum[tid >> 5] = t;
        __syncthreads();
        if (tid < 32) {
            float v = (tid < NTHREADS / 32) ? warpsum[tid] : 0.0f;
#pragma unroll
            for (int o = 4; o > 0; o >>= 1)
                v += __shfl_xor_sync(0xffffffffu, v, o);
            if (tid == 0)
                warpsum[0] = v;
        }
        __syncthreads();
        // All smem reads of stage s done past this barrier -> thread 0 may
        // re-issue TMA into stage s next iteration.

        const float sc = warpsum[0] * (1.0f / (float)L_LEN);

        // Write-through stores: keep the write stream out of L2 so the
        // 75 MB input set converges to full residency across graph replays.
        float4* orow = reinterpret_cast<float4*>(out + (size_t)row * L_LEN);
#pragma unroll
        for (int i = 0; i < ITERS; i++) {
            const int idx = i * NTHREADS + tid;
            float4 v = yv[i];
            v.x *= sc; v.y *= sc; v.z *= sc; v.w *= sc;
            stg_wt_f4(&orow[idx], v);
        }
    }
}

extern "C" void kernel_launch(void* const* d_in, const int* in_sizes, int n_in,
                              void* d_out, int out_size)
{
    const float* x = (const float*)d_in[0];
    const float* y = (const float*)d_in[1];
    float* out = (float*)d_out;

    const int nrows = in_sizes[0] / L_LEN;   // 2304

    cudaFuncSetAttribute(spo2_wt_kernel,
                         cudaFuncAttributeMaxDynamicSharedMemorySize, DYN_SMEM);

    int grid = 3 * 148;                      // 3 persistent CTAs per SM
    if (grid > nrows) grid = nrows;
    spo2_wt_kernel<<<grid, NTHREADS, DYN_SMEM>>>(x, y, out, nrows);
}

// round 13
// speedup vs baseline: 1.3149x; 1.3149x over previous
#include <cuda_runtime.h>
#include <cstdint>

// out = y * (mean(x,-1) + mean(y,-1)),  [64, 36, 4096] fp32, rows = 2304.
//
// R13: return to the R2 structure (one CTA per row, non-persistent, 6
// CTAs/SM, TMA loads, __stcs stores) — the best cold-BW structure measured
// (4815 GB/s vs ~4150 for the persistent pipeline) — and fix its one defect:
// the naked joint wait. x and y get separate mbarriers; the x reduction
// runs as soon as x lands, overlapping the tail of y's TMA. Stores stay
// __stcs (policy sweep complete: cs 14.4 < plain 18.9 < wt 19.0 < el 21.2).

constexpr int L_LEN     = 4096;
constexpr int NTHREADS  = 256;
constexpr int ITERS     = L_LEN / (NTHREADS * 4);   // 4 float4 per thread
constexpr int ROW_BYTES = L_LEN * 4;                // 16 KB

__device__ __forceinline__ uint32_t smem_u32(const void* p) {
    return (uint32_t)__cvta_generic_to_shared(p);
}

__device__ __forceinline__ void mbar_init(uint32_t mbar, uint32_t count) {
    asm volatile("mbarrier.init.shared.b64 [%0], %1;" :: "r"(mbar), "r"(count) : "memory");
}

__device__ __forceinline__ void mbar_expect_tx(uint32_t mbar, uint32_t bytes) {
    asm volatile("mbarrier.arrive.expect_tx.shared.b64 _, [%0], %1;"
                 :: "r"(mbar), "r"(bytes) : "memory");
}

__device__ __forceinline__ void bulk_ld(uint32_t dst_smem, const void* src, uint32_t bytes,
                                        uint32_t mbar) {
    asm volatile(
        "cp.async.bulk.shared::cluster.global.mbarrier::complete_tx::bytes "
        "[%0], [%1], %2, [%3];"
        :: "r"(dst_smem), "l"(src), "r"(bytes), "r"(mbar) : "memory");
}

__device__ __forceinline__ void mbar_wait(uint32_t mbar, uint32_t parity) {
    uint32_t done;
    asm volatile(
        "{\n\t"
        ".reg .pred p;\n\t"
        "mbarrier.try_wait.parity.acquire.cta.shared::cta.b64 p, [%1], %2;\n\t"
        "selp.b32 %0, 1, 0, p;\n\t"
        "}"
        : "=r"(done) : "r"(mbar), "r"(parity) : "memory");
    if (!done) {
        asm volatile(
            "{\n\t"
            ".reg .pred P1;\n\t"
            "WAIT_LOOP_%=:\n\t"
            "mbarrier.try_wait.parity.acquire.cta.shared::cta.b64 P1, [%0], %1, 0x989680;\n\t"
            "@P1 bra.uni WAIT_DONE_%=;\n\t"
            "bra.uni WAIT_LOOP_%=;\n\t"
            "WAIT_DONE_%=:\n\t"
            "}"
            :: "r"(mbar), "r"(parity) : "memory");
    }
}

__global__ __launch_bounds__(NTHREADS)
void spo2_split_wait_kernel(const float* __restrict__ x,
                            const float* __restrict__ y,
                            float* __restrict__ out)
{
    __shared__ alignas(128) float sx[L_LEN];
    __shared__ alignas(128) float sy[L_LEN];
    __shared__ alignas(8) unsigned long long mbar_storage[2];
    __shared__ float warpsum[NTHREADS / 32];

    const int tid = threadIdx.x;
    const uint32_t mbx = smem_u32(&mbar_storage[0]);
    const uint32_t mby = smem_u32(&mbar_storage[1]);
    const size_t row_base = (size_t)blockIdx.x * L_LEN;

    if (tid == 0) {
        mbar_init(mbx, 1);
        mbar_init(mby, 1);
    }
    __syncthreads();

    // Issue both TMAs immediately; separate completion barriers so the x
    // reduction can start while y is still in flight.
    if (tid == 0) {
        mbar_expect_tx(mbx, ROW_BYTES);
        bulk_ld(smem_u32(sx), x + row_base, ROW_BYTES, mbx);
        mbar_expect_tx(mby, ROW_BYTES);
        bulk_ld(smem_u32(sy), y + row_base, ROW_BYTES, mby);
    }

    // ---- x arrives first: reduce it while y's TMA finishes ----
    mbar_wait(mbx, 0);

    const float4* sx4 = reinterpret_cast<const float4*>(sx);
    float t = 0.0f;
#pragma unroll
    for (int i = 0; i < ITERS; i++) {
        float4 a = sx4[i * NTHREADS + tid];
        t += (a.x + a.y) + (a.z + a.w);
    }

    // ---- y: reduce from smem, keep in registers for the scaled store ----
    mbar_wait(mby, 0);

    const float4* sy4 = reinterpret_cast<const float4*>(sy);
    float4 yv[ITERS];
#pragma unroll
    for (int i = 0; i < ITERS; i++) {
        yv[i] = sy4[i * NTHREADS + tid];
        t += (yv[i].x + yv[i].y) + (yv[i].z + yv[i].w);
    }

    // Block reduction -> sc = (sum_x + sum_y)/L
#pragma unroll
    for (int o = 16; o > 0; o >>= 1)
        t += __shfl_xor_sync(0xffffffffu, t, o);
    if ((tid & 31) == 0)
        warpsum[tid >> 5] = t;
    __syncthreads();
    if (tid < 32) {
        float v = (tid < NTHREADS / 32) ? warpsum[tid] : 0.0f;
#pragma unroll
        for (int o = 4; o > 0; o >>= 1)
            v += __shfl_xor_sync(0xffffffffu, v, o);
        if (tid == 0)
            warpsum[0] = v;
    }
    __syncthreads();

    const float sc = warpsum[0] * (1.0f / (float)L_LEN);

    // Streaming (evict-first) stores — the measured-optimal policy.
    float4* orow = reinterpret_cast<float4*>(out + row_base);
#pragma unroll
    for (int i = 0; i < ITERS; i++) {
        float4 v = yv[i];
        v.x *= sc; v.y *= sc; v.z *= sc; v.w *= sc;
        __stcs(&orow[i * NTHREADS + tid], v);
    }
}

extern "C" void kernel_launch(void* const* d_in, const int* in_sizes, int n_in,
                              void* d_out, int out_size)
{
    const float* x = (const float*)d_in[0];
    const float* y = (const float*)d_in[1];
    float* out = (float*)d_out;

    const int rows = in_sizes[0] / L_LEN;   // 2304
    spo2_split_wait_kernel<<<rows, NTHREADS>>>(x, y, out);
}